// round 1
// baseline (speedup 1.0000x reference)
#include <cuda_runtime.h>
#include <math.h>

// ---- problem constants ----
#define Nb   2
#define T    4096
#define Dd   1024
#define H    8
#define E    4
#define Lw   32
#define TC   128          // scan length per (l) block = T / Lw
#define DK   64
#define NT   (Nb*T)       // 8192 rows
#define PC   1568         // 32 (G) + 512 (K) + 512 (V) + 512 (Q)
#define RLEN (Lw + T)     // 4128

#define TQ   32           // queries per attention block
#define WW   63           // window positions staged = TQ + 31
#define SST  260          // smem per-position stride (floats), 260 mod 32 = 4 -> conflict-free

// ---- device scratch (static globals: allocation-free) ----
__device__ float g_Wcat[PC*Dd];
__device__ float g_bias[PC];
__device__ float g_P[(size_t)NT*PC];
__device__ float g_A[Nb*E*T];
__device__ float g_gK[(size_t)Nb*E*T*DK];
__device__ float g_gV[(size_t)Nb*E*T*DK];
__device__ float g_recK[(size_t)Nb*E*RLEN*DK];
__device__ float g_recV[(size_t)Nb*E*RLEN*DK];
__device__ float g_Y[(size_t)NT*H*DK];
__device__ float g_WoT[(size_t)Dd*H*DK];

// ============================================================
// SGEMM (NT form): C[M][Nn] = A[M][K] * B[Nn][K]^T, fp32
// 128x128 tile, BK=8, 256 threads, 8x8 per thread.
// Optional epilogue: sigmoid(v + bias[col]) for col < act_cols.
// ============================================================
template<bool ACT>
__global__ __launch_bounds__(256) void sgemm_nt(
    const float* __restrict__ A, const float* __restrict__ B,
    float* __restrict__ C, int M, int Nn, int K,
    const float* __restrict__ bias, int act_cols)
{
    __shared__ float As[8][128];
    __shared__ float Bs[8][128];
    int tid = threadIdx.x;
    int bm = blockIdx.y, bn = blockIdx.x;
    int lrow = tid >> 1;            // 0..127
    int lcol = (tid & 1) * 4;       // 0 or 4
    int ty = tid >> 4, tx = tid & 15;

    const float* Ap = A + (size_t)(bm*128 + lrow)*K + lcol;
    int nrow = bn*128 + lrow;
    const float* Bp = B + (size_t)nrow*K + lcol;

    float acc[8][8];
    #pragma unroll
    for (int i = 0; i < 8; ++i)
        #pragma unroll
        for (int j = 0; j < 8; ++j) acc[i][j] = 0.f;

    for (int k0 = 0; k0 < K; k0 += 8) {
        float4 va = *(const float4*)(Ap + k0);
        float4 vb = make_float4(0.f,0.f,0.f,0.f);
        if (nrow < Nn) vb = *(const float4*)(Bp + k0);

        __syncthreads();   // previous tile's compute done
        As[lcol+0][lrow] = va.x; As[lcol+1][lrow] = va.y;
        As[lcol+2][lrow] = va.z; As[lcol+3][lrow] = va.w;
        Bs[lcol+0][lrow] = vb.x; Bs[lcol+1][lrow] = vb.y;
        Bs[lcol+2][lrow] = vb.z; Bs[lcol+3][lrow] = vb.w;
        __syncthreads();

        #pragma unroll
        for (int kk = 0; kk < 8; ++kk) {
            float4 a0 = *(const float4*)&As[kk][ty*8];
            float4 a1 = *(const float4*)&As[kk][ty*8+4];
            float4 b0 = *(const float4*)&Bs[kk][tx*8];
            float4 b1 = *(const float4*)&Bs[kk][tx*8+4];
            float ar[8] = {a0.x,a0.y,a0.z,a0.w,a1.x,a1.y,a1.z,a1.w};
            float br[8] = {b0.x,b0.y,b0.z,b0.w,b1.x,b1.y,b1.z,b1.w};
            #pragma unroll
            for (int i = 0; i < 8; ++i)
                #pragma unroll
                for (int j = 0; j < 8; ++j)
                    acc[i][j] = fmaf(ar[i], br[j], acc[i][j]);
        }
    }

    #pragma unroll
    for (int i = 0; i < 8; ++i) {
        int mrow = bm*128 + ty*8 + i;
        float* Cr = C + (size_t)mrow*Nn;
        #pragma unroll
        for (int j = 0; j < 8; ++j) {
            int col = bn*128 + tx*8 + j;
            if (col < Nn) {
                float v = acc[i][j];
                if (ACT && col < act_cols)
                    v = 1.f / (1.f + __expf(-(v + bias[col])));
                Cr[col] = v;
            }
        }
    }
}

// ============================================================
// Gate combine: A = 1 - min(sum_h G, 1);  gK/gV = sum_h G * K/V
// one block per (n,t), 256 threads = (e,d)
// ============================================================
__global__ __launch_bounds__(256) void gate_combine()
{
    int row = blockIdx.x;          // n*T + t
    int n = row / T, t = row - n*T;
    __shared__ float sG[H*E];
    int tid = threadIdx.x;
    const float* Pr = g_P + (size_t)row*PC;
    if (tid < H*E) sG[tid] = Pr[tid];
    __syncthreads();
    if (tid < E) {
        float s = 0.f;
        #pragma unroll
        for (int h = 0; h < H; ++h) s += sG[h*E + tid];
        g_A[(n*E + tid)*T + t] = 1.f - fminf(s, 1.f);
    }
    int e = tid >> 6, d = tid & 63;
    float sk = 0.f, sv = 0.f;
    #pragma unroll
    for (int h = 0; h < H; ++h) {
        float g = sG[h*E + e];
        sk = fmaf(g, Pr[32  + h*64 + d], sk);
        sv = fmaf(g, Pr[544 + h*64 + d], sv);
    }
    size_t o = ((size_t)(n*E + e)*T + t)*DK + d;
    g_gK[o] = sk;
    g_gV[o] = sv;
}

// ============================================================
// Scan: 256 blocks = (n,e,l); 128 threads (first 64: K, next 64: V)
// rec[p<32] = init; rec[32+t] = state after step t
// ============================================================
__global__ __launch_bounds__(128) void scan_kernel(
    const float* __restrict__ initK, const float* __restrict__ initV)
{
    int b = blockIdx.x;
    int l = b % Lw, e = (b / Lw) % E, n = b / (Lw*E);
    int tid = threadIdx.x;
    bool isV = tid >= 64;
    int d = tid & 63;
    const float* init = isV ? initV : initK;
    const float* g    = isV ? g_gV  : g_gK;
    float*       rec  = isV ? g_recV : g_recK;

    float st = init[(e*Lw + l)*DK + d];
    size_t base = (size_t)(n*E + e);
    rec[(base*RLEN + l)*DK + d] = st;               // init row
    const float* Arow   = g_A + base*T;
    const float* grow   = g   + base*T*(size_t)DK;
    float*       recrow = rec + (base*RLEN + Lw)*(size_t)DK;
    int t0 = l*TC;
    #pragma unroll 4
    for (int c = 0; c < TC; ++c) {
        int t = t0 + c;
        float a = Arow[t];
        st = fmaf(a, st, grow[(size_t)t*DK + d]);
        recrow[(size_t)t*DK + d] = st;
    }
}

// ============================================================
// Attention: block = (n, 32-query tile); 256 threads = (h, tq)
// stage 63-pos x 4-expert K/V window in smem; two-pass softmax.
// ============================================================
extern __shared__ float sm_att[];

__global__ __launch_bounds__(256, 1) void attention_kernel()
{
    float* Ks = sm_att;
    float* Vs = sm_att + WW*SST;
    int bid = blockIdx.x;
    int n    = bid / (T/TQ);
    int tile = bid % (T/TQ);
    int t0 = tile*TQ;
    int tid = threadIdx.x;

    // stage K/V window: positions 1+t0 .. 1+t0+62
    for (int i = tid; i < WW*E*16; i += 256) {
        int w   = i >> 6;          // / (E*16)
        int rem = i & 63;
        int e = rem >> 4, d4 = rem & 15;
        size_t go = (((size_t)(n*E + e))*RLEN + (1 + t0 + w))*DK + d4*4;
        float4 kv = *(const float4*)(g_recK + go);
        float4 vv = *(const float4*)(g_recV + go);
        int so = w*SST + e*64 + d4*4;
        *(float4*)(Ks + so) = kv;
        *(float4*)(Vs + so) = vv;
    }
    __syncthreads();

    int h = tid & 7, tq = tid >> 3;
    int t = t0 + tq;
    float4 q[16];
    const float* Qp = g_P + (size_t)(n*T + t)*PC + 1056 + h*64;
    #pragma unroll
    for (int i = 0; i < 16; ++i) q[i] = *(const float4*)(Qp + i*4);

    // pass 1: running max of raw scores
    float m = -1e30f;
    for (int e = 0; e < E; ++e) {
        for (int l = 0; l < Lw; ++l) {
            const float* kp = Ks + (tq + l)*SST + e*64;
            float s = 0.f;
            #pragma unroll
            for (int i = 0; i < 16; ++i) {
                float4 k4 = *(const float4*)(kp + i*4);
                s = fmaf(q[i].x,k4.x, fmaf(q[i].y,k4.y,
                    fmaf(q[i].z,k4.z, fmaf(q[i].w,k4.w, s))));
            }
            m = fmaxf(m, s);
        }
    }

    // pass 2: exp + V accumulate
    float sum = 0.f;
    float4 acc[16];
    #pragma unroll
    for (int i = 0; i < 16; ++i) acc[i] = make_float4(0.f,0.f,0.f,0.f);

    for (int e = 0; e < E; ++e) {
        for (int l = 0; l < Lw; ++l) {
            const float* kp = Ks + (tq + l)*SST + e*64;
            float s = 0.f;
            #pragma unroll
            for (int i = 0; i < 16; ++i) {
                float4 k4 = *(const float4*)(kp + i*4);
                s = fmaf(q[i].x,k4.x, fmaf(q[i].y,k4.y,
                    fmaf(q[i].z,k4.z, fmaf(q[i].w,k4.w, s))));
            }
            float p = __expf((s - m) * 0.125f);   // 1/sqrt(DK)=0.125
            sum += p;
            const float* vp = Vs + (tq + l)*SST + e*64;
            #pragma unroll
            for (int i = 0; i < 16; ++i) {
                float4 v4 = *(const float4*)(vp + i*4);
                acc[i].x = fmaf(p, v4.x, acc[i].x);
                acc[i].y = fmaf(p, v4.y, acc[i].y);
                acc[i].z = fmaf(p, v4.z, acc[i].z);
                acc[i].w = fmaf(p, v4.w, acc[i].w);
            }
        }
    }

    float inv = 1.f / sum;
    float* Yp = g_Y + (size_t)(n*T + t)*(H*DK) + h*64;
    #pragma unroll
    for (int i = 0; i < 16; ++i) {
        float4 o;
        o.x = acc[i].x*inv; o.y = acc[i].y*inv;
        o.z = acc[i].z*inv; o.w = acc[i].w*inv;
        *(float4*)(Yp + i*4) = o;
    }
}

// ============================================================
// w_O transpose: (512,1024) -> (1024,512) into g_WoT
// ============================================================
__global__ void transpose_wo(const float* __restrict__ src)
{
    __shared__ float tile[32][33];
    int tx = threadIdx.x, ty = threadIdx.y;       // 32 x 8
    int x = blockIdx.x*32 + tx;                   // col in src (0..1023)
    int y = blockIdx.y*32 + ty;                   // row in src (0..511)
    #pragma unroll
    for (int i = 0; i < 32; i += 8)
        tile[ty+i][tx] = src[(size_t)(y+i)*Dd + x];
    __syncthreads();
    int x2 = blockIdx.y*32 + tx;                  // col in dst (0..511)
    int y2 = blockIdx.x*32 + ty;                  // row in dst (0..1023)
    #pragma unroll
    for (int i = 0; i < 32; i += 8)
        g_WoT[(size_t)(y2+i)*(H*DK) + x2] = tile[tx][ty+i];
}

// ============================================================
extern "C" void kernel_launch(void* const* d_in, const int* in_sizes, int n_in,
                              void* d_out, int out_size)
{
    const float* X  = (const float*)d_in[0];
    const float* wG = (const float*)d_in[1];
    const float* bG = (const float*)d_in[2];
    const float* wK = (const float*)d_in[3];
    const float* wV = (const float*)d_in[4];
    const float* wQ = (const float*)d_in[5];
    const float* wO = (const float*)d_in[6];
    const float* iK = (const float*)d_in[7];
    const float* iV = (const float*)d_in[8];
    float* out = (float*)d_out;

    // pack concatenated weight matrix + bias (D2D async copies are capture-safe)
    cudaMemcpyToSymbolAsync(g_Wcat, wG, (size_t)32*Dd*sizeof(float),  0,                          cudaMemcpyDeviceToDevice, 0);
    cudaMemcpyToSymbolAsync(g_Wcat, wK, (size_t)512*Dd*sizeof(float), (size_t)32*Dd*sizeof(float),   cudaMemcpyDeviceToDevice, 0);
    cudaMemcpyToSymbolAsync(g_Wcat, wV, (size_t)512*Dd*sizeof(float), (size_t)544*Dd*sizeof(float),  cudaMemcpyDeviceToDevice, 0);
    cudaMemcpyToSymbolAsync(g_Wcat, wQ, (size_t)512*Dd*sizeof(float), (size_t)1056*Dd*sizeof(float), cudaMemcpyDeviceToDevice, 0);
    cudaMemcpyToSymbolAsync(g_bias, bG, 32*sizeof(float), 0, cudaMemcpyDeviceToDevice, 0);

    transpose_wo<<<dim3(Dd/32, (H*DK)/32), dim3(32,8)>>>(wO);

    float *dWcat, *dBias, *dP, *dY, *dWoT;
    cudaGetSymbolAddress((void**)&dWcat, g_Wcat);
    cudaGetSymbolAddress((void**)&dBias, g_bias);
    cudaGetSymbolAddress((void**)&dP,    g_P);
    cudaGetSymbolAddress((void**)&dY,    g_Y);
    cudaGetSymbolAddress((void**)&dWoT,  g_WoT);

    // 1) fused projection GEMM with sigmoid epilogue on first 32 cols
    sgemm_nt<true><<<dim3((PC+127)/128, NT/128), 256>>>(X, dWcat, dP, NT, PC, Dd, dBias, 32);

    // 2) gates -> A, gK, gV
    gate_combine<<<NT, 256>>>();

    // 3) chunked scans
    scan_kernel<<<Nb*E*Lw, 128>>>(iK, iV);

    // 4) sliding-window attention
    int smem_bytes = 2*WW*SST*sizeof(float);
    cudaFuncSetAttribute(attention_kernel, cudaFuncAttributeMaxDynamicSharedMemorySize, smem_bytes);
    attention_kernel<<<Nb*(T/TQ), 256, smem_bytes>>>();

    // 5) output projection
    sgemm_nt<false><<<dim3(Dd/128, NT/128), 256>>>(dY, dWoT, out, NT, Dd, H*DK, nullptr, 0);
}

// round 2
// speedup vs baseline: 2.7424x; 2.7424x over previous
#include <cuda_runtime.h>
#include <math.h>
#include <stdint.h>

// ---- problem constants ----
#define Nb   2
#define T    4096
#define Dd   1024
#define H    8
#define E    4
#define Lw   32
#define TC   128
#define DK   64
#define NT   (Nb*T)       // 8192
#define PC   1568         // 32 G + 512 K + 512 V + 512 Q
#define RLEN (Lw + T)     // 4128

#define TQ   32
#define WW   63
#define SST  260

// ---- device scratch ----
__device__ float g_Wcat[PC*Dd];
__device__ float g_bias[PC];
__device__ float g_P[(size_t)NT*PC];
__device__ float g_A[Nb*E*T];
__device__ float g_gK[(size_t)Nb*E*T*DK];
__device__ float g_gV[(size_t)Nb*E*T*DK];
__device__ float g_recK[(size_t)Nb*E*RLEN*DK];
__device__ float g_recV[(size_t)Nb*E*RLEN*DK];
__device__ float g_Y[(size_t)NT*H*DK];
__device__ float g_WoT[(size_t)Dd*H*DK];

// ============================================================
// TF32 helpers
// ============================================================
__device__ __forceinline__ uint32_t f2tf32(float f) {
    uint32_t u;
    asm("cvt.rna.tf32.f32 %0, %1;" : "=r"(u) : "f"(f));
    return u;
}

__device__ __forceinline__ void mma_tf32(float4& c,
    uint32_t a0, uint32_t a1, uint32_t a2, uint32_t a3,
    uint32_t b0, uint32_t b1)
{
    asm volatile("mma.sync.aligned.m16n8k8.row.col.f32.tf32.tf32.f32 "
        "{%0,%1,%2,%3}, {%4,%5,%6,%7}, {%8,%9}, {%0,%1,%2,%3};"
        : "+f"(c.x), "+f"(c.y), "+f"(c.z), "+f"(c.w)
        : "r"(a0), "r"(a1), "r"(a2), "r"(a3), "r"(b0), "r"(b1));
}

// ============================================================
// TF32 GEMM (NT): C[M][Nn] = A[M][K] * B[Nn][K]^T
// BM=BN=128, BK=16, 256 threads, warp tile 64x32 (2x4 warps).
// Smem row-major [row][16 k] tiles, double buffered. k-interleave
// inside an mma step is reassociated so uint4 frag loads need no permute.
// ============================================================
template<bool ACT>
__global__ __launch_bounds__(256) void mgemm(
    const float* __restrict__ A, const float* __restrict__ B,
    float* __restrict__ C, int M, int Nn, int K,
    const float* __restrict__ bias, int act_cols)
{
    __shared__ uint32_t As[2][128*16];
    __shared__ uint32_t Bs[2][128*16];

    int tid  = threadIdx.x;
    int bm   = blockIdx.y, bn = blockIdx.x;
    int warp = tid >> 5, lane = tid & 31;
    int wm   = (warp >> 2) * 64;
    int wn   = (warp & 3) * 32;
    int gid  = lane >> 2, tig = lane & 3;

    // staging: thread covers (r0,cq) and (r0+64,cq)
    int r0 = tid >> 2;
    int cq = (tid & 3) * 4;
    const float* Aptr = A + (size_t)(bm*128 + r0)*K + cq;
    int brow0 = bn*128 + r0;
    const float* Bptr = B + (size_t)brow0*K + cq;
    bool bok0 = (brow0      < Nn);
    bool bok1 = (brow0 + 64 < Nn);

    float4 acc[4][4];
    #pragma unroll
    for (int i = 0; i < 4; ++i)
        #pragma unroll
        for (int j = 0; j < 4; ++j) acc[i][j] = make_float4(0.f,0.f,0.f,0.f);

    const float4 z4 = make_float4(0.f,0.f,0.f,0.f);
    int nk = K / 16;

    // prologue: stage 0
    float4 a0 = *(const float4*)(Aptr);
    float4 a1 = *(const float4*)(Aptr + (size_t)64*K);
    float4 b0 = bok0 ? *(const float4*)(Bptr) : z4;
    float4 b1 = bok1 ? *(const float4*)(Bptr + (size_t)64*K) : z4;
    {
        uint32_t* as = As[0]; uint32_t* bs = Bs[0];
        *(uint4*)&as[r0*16 + cq]      = make_uint4(f2tf32(a0.x),f2tf32(a0.y),f2tf32(a0.z),f2tf32(a0.w));
        *(uint4*)&as[(r0+64)*16 + cq] = make_uint4(f2tf32(a1.x),f2tf32(a1.y),f2tf32(a1.z),f2tf32(a1.w));
        *(uint4*)&bs[r0*16 + cq]      = make_uint4(f2tf32(b0.x),f2tf32(b0.y),f2tf32(b0.z),f2tf32(b0.w));
        *(uint4*)&bs[(r0+64)*16 + cq] = make_uint4(f2tf32(b1.x),f2tf32(b1.y),f2tf32(b1.z),f2tf32(b1.w));
    }
    __syncthreads();

    int buf = 0;
    for (int kt = 0; kt < nk; ++kt) {
        // prefetch next stage from gmem
        float4 na0, na1, nb0, nb1;
        bool more = (kt + 1 < nk);
        if (more) {
            int k0 = (kt + 1) * 16;
            na0 = *(const float4*)(Aptr + k0);
            na1 = *(const float4*)(Aptr + (size_t)64*K + k0);
            nb0 = bok0 ? *(const float4*)(Bptr + k0) : z4;
            nb1 = bok1 ? *(const float4*)(Bptr + (size_t)64*K + k0) : z4;
        }

        // compute on current buffer
        {
            const uint32_t* as = As[buf];
            const uint32_t* bs = Bs[buf];
            uint4 af0[4], af1[4], bf[4];
            #pragma unroll
            for (int mf = 0; mf < 4; ++mf) {
                af0[mf] = *(const uint4*)&as[(wm + mf*16 + gid    )*16 + tig*4];
                af1[mf] = *(const uint4*)&as[(wm + mf*16 + gid + 8)*16 + tig*4];
            }
            #pragma unroll
            for (int nf = 0; nf < 4; ++nf)
                bf[nf] = *(const uint4*)&bs[(wn + nf*8 + gid)*16 + tig*4];

            #pragma unroll
            for (int mf = 0; mf < 4; ++mf)
                #pragma unroll
                for (int nf = 0; nf < 4; ++nf) {
                    mma_tf32(acc[mf][nf], af0[mf].x, af1[mf].x, af0[mf].y, af1[mf].y,
                                          bf[nf].x, bf[nf].y);
                    mma_tf32(acc[mf][nf], af0[mf].z, af1[mf].z, af0[mf].w, af1[mf].w,
                                          bf[nf].z, bf[nf].w);
                }
        }

        // stage next into other buffer
        if (more) {
            uint32_t* as = As[buf^1]; uint32_t* bs = Bs[buf^1];
            *(uint4*)&as[r0*16 + cq]      = make_uint4(f2tf32(na0.x),f2tf32(na0.y),f2tf32(na0.z),f2tf32(na0.w));
            *(uint4*)&as[(r0+64)*16 + cq] = make_uint4(f2tf32(na1.x),f2tf32(na1.y),f2tf32(na1.z),f2tf32(na1.w));
            *(uint4*)&bs[r0*16 + cq]      = make_uint4(f2tf32(nb0.x),f2tf32(nb0.y),f2tf32(nb0.z),f2tf32(nb0.w));
            *(uint4*)&bs[(r0+64)*16 + cq] = make_uint4(f2tf32(nb1.x),f2tf32(nb1.y),f2tf32(nb1.z),f2tf32(nb1.w));
        }
        __syncthreads();
        buf ^= 1;
    }

    // epilogue: c0,c1 -> (row gid, col 2t..2t+1); c2,c3 -> row gid+8
    #pragma unroll
    for (int mf = 0; mf < 4; ++mf) {
        int row = bm*128 + wm + mf*16 + gid;
        #pragma unroll
        for (int nf = 0; nf < 4; ++nf) {
            int col = bn*128 + wn + nf*8 + tig*2;
            if (col < Nn) {
                float4 v = acc[mf][nf];
                if (ACT && col < act_cols) {
                    v.x = 1.f/(1.f + __expf(-(v.x + bias[col])));
                    v.y = 1.f/(1.f + __expf(-(v.y + bias[col+1])));
                    v.z = 1.f/(1.f + __expf(-(v.z + bias[col])));
                    v.w = 1.f/(1.f + __expf(-(v.w + bias[col+1])));
                }
                *(float2*)(C + (size_t)row*Nn + col)     = make_float2(v.x, v.y);
                *(float2*)(C + (size_t)(row+8)*Nn + col) = make_float2(v.z, v.w);
            }
        }
    }
}

// ============================================================
// Gate combine
// ============================================================
__global__ __launch_bounds__(256) void gate_combine()
{
    int row = blockIdx.x;
    int n = row / T, t = row - n*T;
    __shared__ float sG[H*E];
    int tid = threadIdx.x;
    const float* Pr = g_P + (size_t)row*PC;
    if (tid < H*E) sG[tid] = Pr[tid];
    __syncthreads();
    if (tid < E) {
        float s = 0.f;
        #pragma unroll
        for (int h = 0; h < H; ++h) s += sG[h*E + tid];
        g_A[(n*E + tid)*T + t] = 1.f - fminf(s, 1.f);
    }
    int e = tid >> 6, d = tid & 63;
    float sk = 0.f, sv = 0.f;
    #pragma unroll
    for (int h = 0; h < H; ++h) {
        float g = sG[h*E + e];
        sk = fmaf(g, Pr[32  + h*64 + d], sk);
        sv = fmaf(g, Pr[544 + h*64 + d], sv);
    }
    size_t o = ((size_t)(n*E + e)*T + t)*DK + d;
    g_gK[o] = sk;
    g_gV[o] = sv;
}

// ============================================================
// Scan: software-pipelined, A staged in smem, g prefetched 8 ahead
// ============================================================
__global__ __launch_bounds__(128) void scan_kernel(
    const float* __restrict__ initK, const float* __restrict__ initV)
{
    __shared__ float sa[TC];
    int b = blockIdx.x;
    int l = b % Lw, e = (b / Lw) % E, n = b / (Lw*E);
    int tid = threadIdx.x;
    bool isV = tid >= 64;
    int d = tid & 63;
    const float* init = isV ? initV : initK;
    const float* g    = isV ? g_gV  : g_gK;
    float*       rec  = isV ? g_recV : g_recK;

    size_t base = (size_t)(n*E + e);
    int t0 = l*TC;
    const float* Arow = g_A + base*T + t0;
    if (tid < TC) sa[tid] = Arow[tid];
    __syncthreads();

    float st = init[(e*Lw + l)*DK + d];
    rec[(base*RLEN + l)*DK + d] = st;                 // init row
    const float* grow   = g   + (base*T   + t0)*(size_t)DK + d;
    float*       recrow = rec + (base*RLEN + Lw + t0)*(size_t)DK + d;

    float gbuf[8];
    #pragma unroll
    for (int j = 0; j < 8; ++j) gbuf[j] = grow[(size_t)j*DK];

    for (int c0 = 0; c0 < TC; c0 += 8) {
        float gn[8];
        if (c0 + 8 < TC) {
            #pragma unroll
            for (int j = 0; j < 8; ++j) gn[j] = grow[(size_t)(c0+8+j)*DK];
        }
        #pragma unroll
        for (int j = 0; j < 8; ++j) {
            st = fmaf(sa[c0+j], st, gbuf[j]);
            recrow[(size_t)(c0+j)*DK] = st;
        }
        #pragma unroll
        for (int j = 0; j < 8; ++j) gbuf[j] = gn[j];
    }
}

// ============================================================
// Attention: online softmax, single pass over 128 window positions
// ============================================================
extern __shared__ float sm_att[];

__global__ __launch_bounds__(256, 1) void attention_kernel()
{
    float* Ks = sm_att;
    float* Vs = sm_att + WW*SST;
    int bid = blockIdx.x;
    int n    = bid / (T/TQ);
    int tile = bid % (T/TQ);
    int t0 = tile*TQ;
    int tid = threadIdx.x;

    for (int i = tid; i < WW*E*16; i += 256) {
        int w   = i >> 6;
        int rem = i & 63;
        int e = rem >> 4, d4 = rem & 15;
        size_t go = (((size_t)(n*E + e))*RLEN + (1 + t0 + w))*DK + d4*4;
        float4 kv = *(const float4*)(g_recK + go);
        float4 vv = *(const float4*)(g_recV + go);
        int so = w*SST + e*64 + d4*4;
        *(float4*)(Ks + so) = kv;
        *(float4*)(Vs + so) = vv;
    }
    __syncthreads();

    int h = tid & 7, tq = tid >> 3;
    int t = t0 + tq;
    float4 q[16];
    const float* Qp = g_P + (size_t)(n*T + t)*PC + 1056 + h*64;
    #pragma unroll
    for (int i = 0; i < 16; ++i) q[i] = *(const float4*)(Qp + i*4);

    float m = -1e30f, sum = 0.f;
    float4 acc[16];
    #pragma unroll
    for (int i = 0; i < 16; ++i) acc[i] = make_float4(0.f,0.f,0.f,0.f);

    for (int e = 0; e < E; ++e) {
        for (int l = 0; l < Lw; ++l) {
            const float* kp = Ks + (tq + l)*SST + e*64;
            float s = 0.f;
            #pragma unroll
            for (int i = 0; i < 16; ++i) {
                float4 k4 = *(const float4*)(kp + i*4);
                s = fmaf(q[i].x,k4.x, fmaf(q[i].y,k4.y,
                    fmaf(q[i].z,k4.z, fmaf(q[i].w,k4.w, s))));
            }
            s *= 0.125f;                       // 1/sqrt(DK)
            if (s > m) {
                float f = __expf(m - s);
                sum *= f;
                #pragma unroll
                for (int i = 0; i < 16; ++i) {
                    acc[i].x *= f; acc[i].y *= f; acc[i].z *= f; acc[i].w *= f;
                }
                m = s;
            }
            float p = __expf(s - m);
            sum += p;
            const float* vp = Vs + (tq + l)*SST + e*64;
            #pragma unroll
            for (int i = 0; i < 16; ++i) {
                float4 v4 = *(const float4*)(vp + i*4);
                acc[i].x = fmaf(p, v4.x, acc[i].x);
                acc[i].y = fmaf(p, v4.y, acc[i].y);
                acc[i].z = fmaf(p, v4.z, acc[i].z);
                acc[i].w = fmaf(p, v4.w, acc[i].w);
            }
        }
    }

    float inv = 1.f / sum;
    float* Yp = g_Y + (size_t)(n*T + t)*(H*DK) + h*64;
    #pragma unroll
    for (int i = 0; i < 16; ++i) {
        float4 o;
        o.x = acc[i].x*inv; o.y = acc[i].y*inv;
        o.z = acc[i].z*inv; o.w = acc[i].w*inv;
        *(float4*)(Yp + i*4) = o;
    }
}

// ============================================================
// w_O transpose: (512,1024) -> (1024,512)
// ============================================================
__global__ void transpose_wo(const float* __restrict__ src)
{
    __shared__ float tile[32][33];
    int tx = threadIdx.x, ty = threadIdx.y;
    int x = blockIdx.x*32 + tx;
    int y = blockIdx.y*32 + ty;
    #pragma unroll
    for (int i = 0; i < 32; i += 8)
        tile[ty+i][tx] = src[(size_t)(y+i)*Dd + x];
    __syncthreads();
    int x2 = blockIdx.y*32 + tx;
    int y2 = blockIdx.x*32 + ty;
    #pragma unroll
    for (int i = 0; i < 32; i += 8)
        g_WoT[(size_t)(y2+i)*(H*DK) + x2] = tile[tx][ty+i];
}

// ============================================================
extern "C" void kernel_launch(void* const* d_in, const int* in_sizes, int n_in,
                              void* d_out, int out_size)
{
    const float* X  = (const float*)d_in[0];
    const float* wG = (const float*)d_in[1];
    const float* bG = (const float*)d_in[2];
    const float* wK = (const float*)d_in[3];
    const float* wV = (const float*)d_in[4];
    const float* wQ = (const float*)d_in[5];
    const float* wO = (const float*)d_in[6];
    const float* iK = (const float*)d_in[7];
    const float* iV = (const float*)d_in[8];
    float* out = (float*)d_out;

    cudaMemcpyToSymbolAsync(g_Wcat, wG, (size_t)32*Dd*sizeof(float),  0,                             cudaMemcpyDeviceToDevice, 0);
    cudaMemcpyToSymbolAsync(g_Wcat, wK, (size_t)512*Dd*sizeof(float), (size_t)32*Dd*sizeof(float),   cudaMemcpyDeviceToDevice, 0);
    cudaMemcpyToSymbolAsync(g_Wcat, wV, (size_t)512*Dd*sizeof(float), (size_t)544*Dd*sizeof(float),  cudaMemcpyDeviceToDevice, 0);
    cudaMemcpyToSymbolAsync(g_Wcat, wQ, (size_t)512*Dd*sizeof(float), (size_t)1056*Dd*sizeof(float), cudaMemcpyDeviceToDevice, 0);
    cudaMemcpyToSymbolAsync(g_bias, bG, 32*sizeof(float), 0, cudaMemcpyDeviceToDevice, 0);

    transpose_wo<<<dim3(Dd/32, (H*DK)/32), dim3(32,8)>>>(wO);

    float *dWcat, *dBias, *dP, *dY, *dWoT;
    cudaGetSymbolAddress((void**)&dWcat, g_Wcat);
    cudaGetSymbolAddress((void**)&dBias, g_bias);
    cudaGetSymbolAddress((void**)&dP,    g_P);
    cudaGetSymbolAddress((void**)&dY,    g_Y);
    cudaGetSymbolAddress((void**)&dWoT,  g_WoT);

    // 1) fused projection GEMM (tf32 tensor cores) + sigmoid epilogue on G cols
    mgemm<true><<<dim3((PC+127)/128, NT/128), 256>>>(X, dWcat, dP, NT, PC, Dd, dBias, 32);

    // 2) gates -> A, gK, gV
    gate_combine<<<NT, 256>>>();

    // 3) chunked scans (pipelined)
    scan_kernel<<<Nb*E*Lw, 128>>>(iK, iV);

    // 4) sliding-window attention (online softmax)
    int smem_bytes = 2*WW*SST*sizeof(float);
    cudaFuncSetAttribute(attention_kernel, cudaFuncAttributeMaxDynamicSharedMemorySize, smem_bytes);
    attention_kernel<<<Nb*(T/TQ), 256, smem_bytes>>>();

    // 5) output projection (tf32 tensor cores)
    mgemm<false><<<dim3(Dd/128, NT/128), 256>>>(dY, dWoT, out, NT, Dd, H*DK, nullptr, 0);
}

// round 3
// speedup vs baseline: 3.1133x; 1.1353x over previous
#include <cuda_runtime.h>
#include <math.h>
#include <stdint.h>

// ---- problem constants ----
#define Nb   2
#define T    4096
#define Dd   1024
#define H    8
#define E    4
#define Lw   32
#define TC   128
#define DK   64
#define NT   (Nb*T)       // 8192
#define PC   1568         // 32 G + 512 K + 512 V + 512 Q
#define RLEN (Lw + T)     // 4128

#define TQ   32
#define WW   63
#define SST  260

#define STAGES 3

// ---- device scratch ----
__device__ float    g_Wcat[PC*Dd];
__device__ float    g_bias[PC];
__device__ uint32_t g_Xtf[(size_t)NT*Dd];
__device__ float    g_P[(size_t)NT*PC];
__device__ float    g_A[Nb*E*T];
__device__ float    g_gK[(size_t)Nb*E*T*DK];
__device__ float    g_gV[(size_t)Nb*E*T*DK];
__device__ float    g_recK[(size_t)Nb*E*RLEN*DK];
__device__ float    g_recV[(size_t)Nb*E*RLEN*DK];
__device__ float    g_Y[(size_t)NT*H*DK];
__device__ float    g_WoT[(size_t)Dd*H*DK];

// ============================================================
// TF32 helpers
// ============================================================
__device__ __forceinline__ uint32_t f2tf32(float f) {
    uint32_t u;
    asm("cvt.rna.tf32.f32 %0, %1;" : "=r"(u) : "f"(f));
    return u;
}

__device__ __forceinline__ void mma_tf32(float4& c,
    uint32_t a0, uint32_t a1, uint32_t a2, uint32_t a3,
    uint32_t b0, uint32_t b1)
{
    asm volatile("mma.sync.aligned.m16n8k8.row.col.f32.tf32.tf32.f32 "
        "{%0,%1,%2,%3}, {%4,%5,%6,%7}, {%8,%9}, {%0,%1,%2,%3};"
        : "+f"(c.x), "+f"(c.y), "+f"(c.z), "+f"(c.w)
        : "r"(a0), "r"(a1), "r"(a2), "r"(a3), "r"(b0), "r"(b1));
}

__device__ __forceinline__ void cp16(uint32_t dst, const void* src, int sz) {
    asm volatile("cp.async.cg.shared.global [%0], [%1], 16, %2;"
                 :: "r"(dst), "l"(src), "r"(sz));
}
__device__ __forceinline__ void cp_commit() {
    asm volatile("cp.async.commit_group;");
}
__device__ __forceinline__ void cp_wait1() {
    asm volatile("cp.async.wait_group 1;");
}

// ============================================================
// TF32 GEMM (NT), operands PRE-CONVERTED to tf32 bits in gmem.
// BM=256, BN=128, BK=16. 256 threads, 8 warps of 64x64 tiles.
// 3-stage cp.async pipeline. C[M][Nn] = A[M][K] * B[Nn][K]^T.
// ============================================================
template<bool ACT>
__global__ __launch_bounds__(256) void mgemm(
    const uint32_t* __restrict__ A, const uint32_t* __restrict__ B,
    float* __restrict__ C, int M, int Nn, int K,
    const float* __restrict__ bias, int act_cols)
{
    extern __shared__ uint32_t smem[];
    uint32_t* Asm = smem;                 // STAGES * 256*16
    uint32_t* Bsm = smem + STAGES*256*16; // STAGES * 128*16

    int tid  = threadIdx.x;
    int bm   = blockIdx.y, bn = blockIdx.x;
    int warp = tid >> 5, lane = tid & 31;
    int wm   = (warp >> 1) * 64;          // 0,64,128,192
    int wn   = (warp & 1) * 64;           // 0,64
    int gid  = lane >> 2, tig = lane & 3;

    int r0 = tid >> 2;                    // 0..63
    int cq = (tid & 3) * 4;               // 0,4,8,12

    const uint32_t* Ab = A + (size_t)(bm*256 + r0)*K + cq;
    int brow0 = bn*128 + r0;
    int sz0 = (brow0      < Nn) ? 16 : 0;
    int sz1 = (brow0 + 64 < Nn) ? 16 : 0;
    const uint32_t* Bb0 = B + (size_t)(sz0 ? brow0      : 0)*K + cq;
    const uint32_t* Bb1 = B + (size_t)(sz1 ? brow0 + 64 : 0)*K + cq;

    uint32_t sA = (uint32_t)__cvta_generic_to_shared(Asm) + (r0*16 + cq)*4;
    uint32_t sB = (uint32_t)__cvta_generic_to_shared(Bsm) + (r0*16 + cq)*4;

    int nk = K / 16;

    auto issue = [&](int kt, int s) {
        uint32_t sa = sA + s*(256*16*4);
        uint32_t sb = sB + s*(128*16*4);
        const uint32_t* ap = Ab + kt*16;
        #pragma unroll
        for (int i = 0; i < 4; ++i)
            cp16(sa + i*(64*16*4), ap + (size_t)i*64*K, 16);
        cp16(sb,             Bb0 + kt*16, sz0);
        cp16(sb + 64*16*4,   Bb1 + kt*16, sz1);
    };

    float4 acc[4][8];
    #pragma unroll
    for (int i = 0; i < 4; ++i)
        #pragma unroll
        for (int j = 0; j < 8; ++j) acc[i][j] = make_float4(0.f,0.f,0.f,0.f);

    // prologue: stages 0,1
    issue(0, 0); cp_commit();
    issue(1, 1); cp_commit();

    for (int kt = 0; kt < nk; ++kt) {
        cp_wait1();
        __syncthreads();

        int buf = kt % STAGES;
        const uint32_t* as = Asm + buf*(256*16);
        const uint32_t* bs = Bsm + buf*(128*16);

        uint4 af0[4], af1[4], bf[8];
        #pragma unroll
        for (int mf = 0; mf < 4; ++mf) {
            af0[mf] = *(const uint4*)&as[(wm + mf*16 + gid    )*16 + tig*4];
            af1[mf] = *(const uint4*)&as[(wm + mf*16 + gid + 8)*16 + tig*4];
        }
        #pragma unroll
        for (int nf = 0; nf < 8; ++nf)
            bf[nf] = *(const uint4*)&bs[(wn + nf*8 + gid)*16 + tig*4];

        #pragma unroll
        for (int mf = 0; mf < 4; ++mf)
            #pragma unroll
            for (int nf = 0; nf < 8; ++nf) {
                mma_tf32(acc[mf][nf], af0[mf].x, af1[mf].x, af0[mf].y, af1[mf].y,
                                      bf[nf].x, bf[nf].y);
                mma_tf32(acc[mf][nf], af0[mf].z, af1[mf].z, af0[mf].w, af1[mf].w,
                                      bf[nf].z, bf[nf].w);
            }

        int kn = kt + (STAGES - 1);
        if (kn < nk) issue(kn, kn % STAGES);
        cp_commit();
    }

    // epilogue
    #pragma unroll
    for (int mf = 0; mf < 4; ++mf) {
        int row = bm*256 + wm + mf*16 + gid;
        #pragma unroll
        for (int nf = 0; nf < 8; ++nf) {
            int col = bn*128 + wn + nf*8 + tig*2;
            if (col < Nn) {
                float4 v = acc[mf][nf];
                if (ACT && col < act_cols) {
                    v.x = 1.f/(1.f + __expf(-(v.x + bias[col])));
                    v.y = 1.f/(1.f + __expf(-(v.y + bias[col+1])));
                    v.z = 1.f/(1.f + __expf(-(v.z + bias[col])));
                    v.w = 1.f/(1.f + __expf(-(v.w + bias[col+1])));
                }
                *(float2*)(C + (size_t)row*Nn + col)     = make_float2(v.x, v.y);
                *(float2*)(C + (size_t)(row+8)*Nn + col) = make_float2(v.z, v.w);
            }
        }
    }
}

// ============================================================
// one-shot tf32 converters
// ============================================================
__global__ void cvt_x(const float4* __restrict__ X, uint4* __restrict__ out, int n4)
{
    int i = blockIdx.x*blockDim.x + threadIdx.x;
    if (i < n4) {
        float4 v = X[i];
        out[i] = make_uint4(f2tf32(v.x), f2tf32(v.y), f2tf32(v.z), f2tf32(v.w));
    }
}

__global__ void cvt_w(uint32_t* __restrict__ W, int n4)
{
    int i = blockIdx.x*blockDim.x + threadIdx.x;
    if (i < n4) {
        float4 v = *(const float4*)(W + i*4);
        *(uint4*)(W + i*4) = make_uint4(f2tf32(v.x), f2tf32(v.y), f2tf32(v.z), f2tf32(v.w));
    }
}

// ============================================================
// Gate combine
// ============================================================
__global__ __launch_bounds__(256) void gate_combine()
{
    int row = blockIdx.x;
    int n = row / T, t = row - n*T;
    __shared__ float sG[H*E];
    int tid = threadIdx.x;
    const float* Pr = g_P + (size_t)row*PC;
    if (tid < H*E) sG[tid] = Pr[tid];
    __syncthreads();
    if (tid < E) {
        float s = 0.f;
        #pragma unroll
        for (int h = 0; h < H; ++h) s += sG[h*E + tid];
        g_A[(n*E + tid)*T + t] = 1.f - fminf(s, 1.f);
    }
    int e = tid >> 6, d = tid & 63;
    float sk = 0.f, sv = 0.f;
    #pragma unroll
    for (int h = 0; h < H; ++h) {
        float g = sG[h*E + e];
        sk = fmaf(g, Pr[32  + h*64 + d], sk);
        sv = fmaf(g, Pr[544 + h*64 + d], sv);
    }
    size_t o = ((size_t)(n*E + e)*T + t)*DK + d;
    g_gK[o] = sk;
    g_gV[o] = sv;
}

// ============================================================
// Scan (pipelined)
// ============================================================
__global__ __launch_bounds__(128) void scan_kernel(
    const float* __restrict__ initK, const float* __restrict__ initV)
{
    __shared__ float sa[TC];
    int b = blockIdx.x;
    int l = b % Lw, e = (b / Lw) % E, n = b / (Lw*E);
    int tid = threadIdx.x;
    bool isV = tid >= 64;
    int d = tid & 63;
    const float* init = isV ? initV : initK;
    const float* g    = isV ? g_gV  : g_gK;
    float*       rec  = isV ? g_recV : g_recK;

    size_t base = (size_t)(n*E + e);
    int t0 = l*TC;
    const float* Arow = g_A + base*T + t0;
    if (tid < TC) sa[tid] = Arow[tid];
    __syncthreads();

    float st = init[(e*Lw + l)*DK + d];
    rec[(base*RLEN + l)*DK + d] = st;
    const float* grow   = g   + (base*T   + t0)*(size_t)DK + d;
    float*       recrow = rec + (base*RLEN + Lw + t0)*(size_t)DK + d;

    float gbuf[8];
    #pragma unroll
    for (int j = 0; j < 8; ++j) gbuf[j] = grow[(size_t)j*DK];

    for (int c0 = 0; c0 < TC; c0 += 8) {
        float gn[8];
        if (c0 + 8 < TC) {
            #pragma unroll
            for (int j = 0; j < 8; ++j) gn[j] = grow[(size_t)(c0+8+j)*DK];
        }
        #pragma unroll
        for (int j = 0; j < 8; ++j) {
            st = fmaf(sa[c0+j], st, gbuf[j]);
            recrow[(size_t)(c0+j)*DK] = st;
        }
        #pragma unroll
        for (int j = 0; j < 8; ++j) gbuf[j] = gn[j];
    }
}

// ============================================================
// Attention: online softmax; writes Y pre-rounded to tf32
// ============================================================
extern __shared__ float sm_att[];

__global__ __launch_bounds__(256, 1) void attention_kernel()
{
    float* Ks = sm_att;
    float* Vs = sm_att + WW*SST;
    int bid = blockIdx.x;
    int n    = bid / (T/TQ);
    int tile = bid % (T/TQ);
    int t0 = tile*TQ;
    int tid = threadIdx.x;

    for (int i = tid; i < WW*E*16; i += 256) {
        int w   = i >> 6;
        int rem = i & 63;
        int e = rem >> 4, d4 = rem & 15;
        size_t go = (((size_t)(n*E + e))*RLEN + (1 + t0 + w))*DK + d4*4;
        float4 kv = *(const float4*)(g_recK + go);
        float4 vv = *(const float4*)(g_recV + go);
        int so = w*SST + e*64 + d4*4;
        *(float4*)(Ks + so) = kv;
        *(float4*)(Vs + so) = vv;
    }
    __syncthreads();

    int h = tid & 7, tq = tid >> 3;
    int t = t0 + tq;
    float4 q[16];
    const float* Qp = g_P + (size_t)(n*T + t)*PC + 1056 + h*64;
    #pragma unroll
    for (int i = 0; i < 16; ++i) q[i] = *(const float4*)(Qp + i*4);

    float m = -1e30f, sum = 0.f;
    float4 acc[16];
    #pragma unroll
    for (int i = 0; i < 16; ++i) acc[i] = make_float4(0.f,0.f,0.f,0.f);

    for (int e = 0; e < E; ++e) {
        for (int l = 0; l < Lw; ++l) {
            const float* kp = Ks + (tq + l)*SST + e*64;
            float s = 0.f;
            #pragma unroll
            for (int i = 0; i < 16; ++i) {
                float4 k4 = *(const float4*)(kp + i*4);
                s = fmaf(q[i].x,k4.x, fmaf(q[i].y,k4.y,
                    fmaf(q[i].z,k4.z, fmaf(q[i].w,k4.w, s))));
            }
            s *= 0.125f;
            if (s > m) {
                float f = __expf(m - s);
                sum *= f;
                #pragma unroll
                for (int i = 0; i < 16; ++i) {
                    acc[i].x *= f; acc[i].y *= f; acc[i].z *= f; acc[i].w *= f;
                }
                m = s;
            }
            float p = __expf(s - m);
            sum += p;
            const float* vp = Vs + (tq + l)*SST + e*64;
            #pragma unroll
            for (int i = 0; i < 16; ++i) {
                float4 v4 = *(const float4*)(vp + i*4);
                acc[i].x = fmaf(p, v4.x, acc[i].x);
                acc[i].y = fmaf(p, v4.y, acc[i].y);
                acc[i].z = fmaf(p, v4.z, acc[i].z);
                acc[i].w = fmaf(p, v4.w, acc[i].w);
            }
        }
    }

    float inv = 1.f / sum;
    float* Yp = g_Y + (size_t)(n*T + t)*(H*DK) + h*64;
    #pragma unroll
    for (int i = 0; i < 16; ++i) {
        float4 o;
        o.x = __uint_as_float(f2tf32(acc[i].x*inv));
        o.y = __uint_as_float(f2tf32(acc[i].y*inv));
        o.z = __uint_as_float(f2tf32(acc[i].z*inv));
        o.w = __uint_as_float(f2tf32(acc[i].w*inv));
        *(float4*)(Yp + i*4) = o;
    }
}

// ============================================================
// w_O transpose: (512,1024) -> (1024,512), rounded to tf32
// ============================================================
__global__ void transpose_wo(const float* __restrict__ src)
{
    __shared__ float tile[32][33];
    int tx = threadIdx.x, ty = threadIdx.y;
    int x = blockIdx.x*32 + tx;
    int y = blockIdx.y*32 + ty;
    #pragma unroll
    for (int i = 0; i < 32; i += 8)
        tile[ty+i][tx] = src[(size_t)(y+i)*Dd + x];
    __syncthreads();
    int x2 = blockIdx.y*32 + tx;
    int y2 = blockIdx.x*32 + ty;
    #pragma unroll
    for (int i = 0; i < 32; i += 8)
        g_WoT[(size_t)(y2+i)*(H*DK) + x2] = __uint_as_float(f2tf32(tile[tx][ty+i]));
}

// ============================================================
extern "C" void kernel_launch(void* const* d_in, const int* in_sizes, int n_in,
                              void* d_out, int out_size)
{
    const float* X  = (const float*)d_in[0];
    const float* wG = (const float*)d_in[1];
    const float* bG = (const float*)d_in[2];
    const float* wK = (const float*)d_in[3];
    const float* wV = (const float*)d_in[4];
    const float* wQ = (const float*)d_in[5];
    const float* wO = (const float*)d_in[6];
    const float* iK = (const float*)d_in[7];
    const float* iV = (const float*)d_in[8];
    float* out = (float*)d_out;

    cudaMemcpyToSymbolAsync(g_Wcat, wG, (size_t)32*Dd*sizeof(float),  0,                             cudaMemcpyDeviceToDevice, 0);
    cudaMemcpyToSymbolAsync(g_Wcat, wK, (size_t)512*Dd*sizeof(float), (size_t)32*Dd*sizeof(float),   cudaMemcpyDeviceToDevice, 0);
    cudaMemcpyToSymbolAsync(g_Wcat, wV, (size_t)512*Dd*sizeof(float), (size_t)544*Dd*sizeof(float),  cudaMemcpyDeviceToDevice, 0);
    cudaMemcpyToSymbolAsync(g_Wcat, wQ, (size_t)512*Dd*sizeof(float), (size_t)1056*Dd*sizeof(float), cudaMemcpyDeviceToDevice, 0);
    cudaMemcpyToSymbolAsync(g_bias, bG, 32*sizeof(float), 0, cudaMemcpyDeviceToDevice, 0);

    float *dWcat, *dBias, *dP, *dY, *dWoT;
    uint32_t *dXtf;
    cudaGetSymbolAddress((void**)&dWcat, g_Wcat);
    cudaGetSymbolAddress((void**)&dBias, g_bias);
    cudaGetSymbolAddress((void**)&dP,    g_P);
    cudaGetSymbolAddress((void**)&dY,    g_Y);
    cudaGetSymbolAddress((void**)&dWoT,  g_WoT);
    cudaGetSymbolAddress((void**)&dXtf,  g_Xtf);

    // pre-round operands to tf32
    cvt_w<<<(PC*Dd/4 + 255)/256, 256>>>(( uint32_t*)dWcat, PC*Dd/4);
    cvt_x<<<((NT*Dd/4) + 255)/256, 256>>>((const float4*)X, (uint4*)dXtf, NT*Dd/4);
    transpose_wo<<<dim3(Dd/32, (H*DK)/32), dim3(32,8)>>>(wO);

    int gsmem = STAGES*(256 + 128)*16*4;   // 73728 B
    cudaFuncSetAttribute(mgemm<true>,  cudaFuncAttributeMaxDynamicSharedMemorySize, gsmem);
    cudaFuncSetAttribute(mgemm<false>, cudaFuncAttributeMaxDynamicSharedMemorySize, gsmem);

    // 1) fused projection GEMM
    mgemm<true><<<dim3((PC+127)/128, NT/256), 256, gsmem>>>(
        dXtf, (const uint32_t*)dWcat, dP, NT, PC, Dd, dBias, 32);

    // 2) gates
    gate_combine<<<NT, 256>>>();

    // 3) scans
    scan_kernel<<<Nb*E*Lw, 128>>>(iK, iV);

    // 4) attention
    int smem_bytes = 2*WW*SST*sizeof(float);
    cudaFuncSetAttribute(attention_kernel, cudaFuncAttributeMaxDynamicSharedMemorySize, smem_bytes);
    attention_kernel<<<Nb*(T/TQ), 256, smem_bytes>>>();

    // 5) output projection
    mgemm<false><<<dim3(Dd/128, NT/256), 256, gsmem>>>(
        (const uint32_t*)dY, (const uint32_t*)dWoT, out, NT, Dd, H*DK, nullptr, 0);
}

// round 4
// speedup vs baseline: 3.1234x; 1.0033x over previous
#include <cuda_runtime.h>
#include <math.h>
#include <stdint.h>

// ---- problem constants ----
#define Nb   2
#define T    4096
#define Dd   1024
#define H    8
#define E    4
#define Lw   32
#define TC   128
#define DK   64
#define NT   (Nb*T)       // 8192
#define PC   1568         // 32 G + 512 K + 512 V + 512 Q
#define RLEN (Lw + T)     // 4128

#define TQ   32
#define WW   63
#define SST  260

#define STAGES 3

// ---- device scratch ----
__device__ uint32_t g_Wcat[PC*Dd];      // tf32 bits
__device__ float    g_bias[PC];
__device__ uint32_t g_Xtf[(size_t)NT*Dd];
__device__ float    g_P[(size_t)NT*PC];
__device__ float    g_A[Nb*E*T];
__device__ float    g_gK[(size_t)Nb*E*T*DK];
__device__ float    g_gV[(size_t)Nb*E*T*DK];
__device__ float    g_recK[(size_t)Nb*E*RLEN*DK];
__device__ float    g_recV[(size_t)Nb*E*RLEN*DK];
__device__ float    g_Y[(size_t)NT*H*DK];
__device__ float    g_WoT[(size_t)Dd*H*DK];

// ============================================================
// TF32 helpers
// ============================================================
__device__ __forceinline__ uint32_t f2tf32(float f) {
    uint32_t u;
    asm("cvt.rna.tf32.f32 %0, %1;" : "=r"(u) : "f"(f));
    return u;
}

__device__ __forceinline__ void mma_tf32(float4& c,
    uint32_t a0, uint32_t a1, uint32_t a2, uint32_t a3,
    uint32_t b0, uint32_t b1)
{
    asm volatile("mma.sync.aligned.m16n8k8.row.col.f32.tf32.tf32.f32 "
        "{%0,%1,%2,%3}, {%4,%5,%6,%7}, {%8,%9}, {%0,%1,%2,%3};"
        : "+f"(c.x), "+f"(c.y), "+f"(c.z), "+f"(c.w)
        : "r"(a0), "r"(a1), "r"(a2), "r"(a3), "r"(b0), "r"(b1));
}

__device__ __forceinline__ void cp16(uint32_t dst, const void* src, int sz) {
    asm volatile("cp.async.cg.shared.global [%0], [%1], 16, %2;"
                 :: "r"(dst), "l"(src), "r"(sz));
}
__device__ __forceinline__ void cp_commit() {
    asm volatile("cp.async.commit_group;");
}
__device__ __forceinline__ void cp_wait1() {
    asm volatile("cp.async.wait_group 1;");
}

// ============================================================
// TF32 GEMM (NT), operands pre-converted to tf32 bits.
// BM=128, BN=128, BK=16. 256 threads, 8 warps of 64x32 tiles.
// 3-stage cp.async pipeline, 2 CTAs/SM.
// ============================================================
template<bool ACT>
__global__ __launch_bounds__(256, 2) void mgemm(
    const uint32_t* __restrict__ A, const uint32_t* __restrict__ B,
    float* __restrict__ C, int M, int Nn, int K,
    const float* __restrict__ bias, int act_cols)
{
    extern __shared__ uint32_t smem[];
    uint32_t* Asm = smem;                 // STAGES * 128*16
    uint32_t* Bsm = smem + STAGES*128*16; // STAGES * 128*16

    int tid  = threadIdx.x;
    int bm   = blockIdx.y, bn = blockIdx.x;
    int warp = tid >> 5, lane = tid & 31;
    int wm   = (warp >> 2) * 64;          // 0,64
    int wn   = (warp & 3) * 32;           // 0,32,64,96
    int gid  = lane >> 2, tig = lane & 3;

    int r0 = tid >> 2;                    // 0..63
    int cq = (tid & 3) * 4;               // 0,4,8,12

    const uint32_t* Ab = A + (size_t)(bm*128 + r0)*K + cq;
    int brow0 = bn*128 + r0;
    int sz0 = (brow0      < Nn) ? 16 : 0;
    int sz1 = (brow0 + 64 < Nn) ? 16 : 0;
    const uint32_t* Bb0 = B + (size_t)(sz0 ? brow0      : 0)*K + cq;
    const uint32_t* Bb1 = B + (size_t)(sz1 ? brow0 + 64 : 0)*K + cq;

    uint32_t sA = (uint32_t)__cvta_generic_to_shared(Asm) + (r0*16 + cq)*4;
    uint32_t sB = (uint32_t)__cvta_generic_to_shared(Bsm) + (r0*16 + cq)*4;

    int nk = K / 16;

    auto issue = [&](int kt, int s) {
        uint32_t sa = sA + s*(128*16*4);
        uint32_t sb = sB + s*(128*16*4);
        const uint32_t* ap = Ab + kt*16;
        cp16(sa,           ap, 16);
        cp16(sa + 64*16*4, ap + (size_t)64*K, 16);
        cp16(sb,           Bb0 + kt*16, sz0);
        cp16(sb + 64*16*4, Bb1 + kt*16, sz1);
    };

    float4 acc[4][4];
    #pragma unroll
    for (int i = 0; i < 4; ++i)
        #pragma unroll
        for (int j = 0; j < 4; ++j) acc[i][j] = make_float4(0.f,0.f,0.f,0.f);

    issue(0, 0); cp_commit();
    issue(1, 1); cp_commit();

    for (int kt = 0; kt < nk; ++kt) {
        cp_wait1();
        __syncthreads();

        int buf = kt % STAGES;
        const uint32_t* as = Asm + buf*(128*16);
        const uint32_t* bs = Bsm + buf*(128*16);

        uint4 af0[4], af1[4], bf[4];
        #pragma unroll
        for (int mf = 0; mf < 4; ++mf) {
            af0[mf] = *(const uint4*)&as[(wm + mf*16 + gid    )*16 + tig*4];
            af1[mf] = *(const uint4*)&as[(wm + mf*16 + gid + 8)*16 + tig*4];
        }
        #pragma unroll
        for (int nf = 0; nf < 4; ++nf)
            bf[nf] = *(const uint4*)&bs[(wn + nf*8 + gid)*16 + tig*4];

        #pragma unroll
        for (int mf = 0; mf < 4; ++mf)
            #pragma unroll
            for (int nf = 0; nf < 4; ++nf) {
                mma_tf32(acc[mf][nf], af0[mf].x, af1[mf].x, af0[mf].y, af1[mf].y,
                                      bf[nf].x, bf[nf].y);
                mma_tf32(acc[mf][nf], af0[mf].z, af1[mf].z, af0[mf].w, af1[mf].w,
                                      bf[nf].z, bf[nf].w);
            }

        int kn = kt + (STAGES - 1);
        if (kn < nk) issue(kn, kn % STAGES);
        cp_commit();
    }

    #pragma unroll
    for (int mf = 0; mf < 4; ++mf) {
        int row = bm*128 + wm + mf*16 + gid;
        #pragma unroll
        for (int nf = 0; nf < 4; ++nf) {
            int col = bn*128 + wn + nf*8 + tig*2;
            if (col < Nn) {
                float4 v = acc[mf][nf];
                if (ACT && col < act_cols) {
                    v.x = 1.f/(1.f + __expf(-(v.x + bias[col])));
                    v.y = 1.f/(1.f + __expf(-(v.y + bias[col+1])));
                    v.z = 1.f/(1.f + __expf(-(v.z + bias[col])));
                    v.w = 1.f/(1.f + __expf(-(v.w + bias[col+1])));
                }
                *(float2*)(C + (size_t)row*Nn + col)     = make_float2(v.x, v.y);
                *(float2*)(C + (size_t)(row+8)*Nn + col) = make_float2(v.z, v.w);
            }
        }
    }
}

// ============================================================
// fused weight pack + tf32 convert:
// g_Wcat rows [0,32)=wG, [32,544)=wK, [544,1056)=wV, [1056,1568)=wQ
// ============================================================
__global__ void pack_weights(const float4* __restrict__ wG,
                             const float4* __restrict__ wK,
                             const float4* __restrict__ wV,
                             const float4* __restrict__ wQ)
{
    int i = blockIdx.x*blockDim.x + threadIdx.x;   // float4 index
    if (i >= PC*Dd/4) return;
    int row = i / (Dd/4);
    int c4  = i - row*(Dd/4);
    float4 v;
    if (row < 32)        v = wG[row*(Dd/4) + c4];
    else if (row < 544)  v = wK[(row-32)*(Dd/4) + c4];
    else if (row < 1056) v = wV[(row-544)*(Dd/4) + c4];
    else                 v = wQ[(row-1056)*(Dd/4) + c4];
    ((uint4*)g_Wcat)[i] = make_uint4(f2tf32(v.x), f2tf32(v.y), f2tf32(v.z), f2tf32(v.w));
}

__global__ void cvt_x(const float4* __restrict__ X, uint4* __restrict__ out, int n4)
{
    int i = blockIdx.x*blockDim.x + threadIdx.x;
    if (i < n4) {
        float4 v = X[i];
        out[i] = make_uint4(f2tf32(v.x), f2tf32(v.y), f2tf32(v.z), f2tf32(v.w));
    }
}

// ============================================================
// Gate combine
// ============================================================
__global__ __launch_bounds__(256) void gate_combine()
{
    int row = blockIdx.x;
    int n = row / T, t = row - n*T;
    __shared__ float sG[H*E];
    int tid = threadIdx.x;
    const float* Pr = g_P + (size_t)row*PC;
    if (tid < H*E) sG[tid] = Pr[tid];
    __syncthreads();
    if (tid < E) {
        float s = 0.f;
        #pragma unroll
        for (int h = 0; h < H; ++h) s += sG[h*E + tid];
        g_A[(n*E + tid)*T + t] = 1.f - fminf(s, 1.f);
    }
    int e = tid >> 6, d = tid & 63;
    float sk = 0.f, sv = 0.f;
    #pragma unroll
    for (int h = 0; h < H; ++h) {
        float g = sG[h*E + e];
        sk = fmaf(g, Pr[32  + h*64 + d], sk);
        sv = fmaf(g, Pr[544 + h*64 + d], sv);
    }
    size_t o = ((size_t)(n*E + e)*T + t)*DK + d;
    g_gK[o] = sk;
    g_gV[o] = sv;
}

// ============================================================
// Scan (pipelined)
// ============================================================
__global__ __launch_bounds__(128) void scan_kernel(
    const float* __restrict__ initK, const float* __restrict__ initV)
{
    __shared__ float sa[TC];
    int b = blockIdx.x;
    int l = b % Lw, e = (b / Lw) % E, n = b / (Lw*E);
    int tid = threadIdx.x;
    bool isV = tid >= 64;
    int d = tid & 63;
    const float* init = isV ? initV : initK;
    const float* g    = isV ? g_gV  : g_gK;
    float*       rec  = isV ? g_recV : g_recK;

    size_t base = (size_t)(n*E + e);
    int t0 = l*TC;
    const float* Arow = g_A + base*T + t0;
    if (tid < TC) sa[tid] = Arow[tid];
    __syncthreads();

    float st = init[(e*Lw + l)*DK + d];
    rec[(base*RLEN + l)*DK + d] = st;
    const float* grow   = g   + (base*T   + t0)*(size_t)DK + d;
    float*       recrow = rec + (base*RLEN + Lw + t0)*(size_t)DK + d;

    float gbuf[8];
    #pragma unroll
    for (int j = 0; j < 8; ++j) gbuf[j] = grow[(size_t)j*DK];

    for (int c0 = 0; c0 < TC; c0 += 8) {
        float gn[8];
        if (c0 + 8 < TC) {
            #pragma unroll
            for (int j = 0; j < 8; ++j) gn[j] = grow[(size_t)(c0+8+j)*DK];
        }
        #pragma unroll
        for (int j = 0; j < 8; ++j) {
            st = fmaf(sa[c0+j], st, gbuf[j]);
            recrow[(size_t)(c0+j)*DK] = st;
        }
        #pragma unroll
        for (int j = 0; j < 8; ++j) gbuf[j] = gn[j];
    }
}

// ============================================================
// Attention: online softmax; writes Y pre-rounded to tf32
// ============================================================
extern __shared__ float sm_att[];

__global__ __launch_bounds__(256, 1) void attention_kernel()
{
    float* Ks = sm_att;
    float* Vs = sm_att + WW*SST;
    int bid = blockIdx.x;
    int n    = bid / (T/TQ);
    int tile = bid % (T/TQ);
    int t0 = tile*TQ;
    int tid = threadIdx.x;

    for (int i = tid; i < WW*E*16; i += 256) {
        int w   = i >> 6;
        int rem = i & 63;
        int e = rem >> 4, d4 = rem & 15;
        size_t go = (((size_t)(n*E + e))*RLEN + (1 + t0 + w))*DK + d4*4;
        float4 kv = *(const float4*)(g_recK + go);
        float4 vv = *(const float4*)(g_recV + go);
        int so = w*SST + e*64 + d4*4;
        *(float4*)(Ks + so) = kv;
        *(float4*)(Vs + so) = vv;
    }
    __syncthreads();

    int h = tid & 7, tq = tid >> 3;
    int t = t0 + tq;
    float4 q[16];
    const float* Qp = g_P + (size_t)(n*T + t)*PC + 1056 + h*64;
    #pragma unroll
    for (int i = 0; i < 16; ++i) q[i] = *(const float4*)(Qp + i*4);

    float m = -1e30f, sum = 0.f;
    float4 acc[16];
    #pragma unroll
    for (int i = 0; i < 16; ++i) acc[i] = make_float4(0.f,0.f,0.f,0.f);

    for (int e = 0; e < E; ++e) {
        for (int l = 0; l < Lw; ++l) {
            const float* kp = Ks + (tq + l)*SST + e*64;
            float s = 0.f;
            #pragma unroll
            for (int i = 0; i < 16; ++i) {
                float4 k4 = *(const float4*)(kp + i*4);
                s = fmaf(q[i].x,k4.x, fmaf(q[i].y,k4.y,
                    fmaf(q[i].z,k4.z, fmaf(q[i].w,k4.w, s))));
            }
            s *= 0.125f;
            if (s > m) {
                float f = __expf(m - s);
                sum *= f;
                #pragma unroll
                for (int i = 0; i < 16; ++i) {
                    acc[i].x *= f; acc[i].y *= f; acc[i].z *= f; acc[i].w *= f;
                }
                m = s;
            }
            float p = __expf(s - m);
            sum += p;
            const float* vp = Vs + (tq + l)*SST + e*64;
            #pragma unroll
            for (int i = 0; i < 16; ++i) {
                float4 v4 = *(const float4*)(vp + i*4);
                acc[i].x = fmaf(p, v4.x, acc[i].x);
                acc[i].y = fmaf(p, v4.y, acc[i].y);
                acc[i].z = fmaf(p, v4.z, acc[i].z);
                acc[i].w = fmaf(p, v4.w, acc[i].w);
            }
        }
    }

    float inv = 1.f / sum;
    float* Yp = g_Y + (size_t)(n*T + t)*(H*DK) + h*64;
    #pragma unroll
    for (int i = 0; i < 16; ++i) {
        float4 o;
        o.x = __uint_as_float(f2tf32(acc[i].x*inv));
        o.y = __uint_as_float(f2tf32(acc[i].y*inv));
        o.z = __uint_as_float(f2tf32(acc[i].z*inv));
        o.w = __uint_as_float(f2tf32(acc[i].w*inv));
        *(float4*)(Yp + i*4) = o;
    }
}

// ============================================================
// w_O transpose: (512,1024) -> (1024,512), rounded to tf32
// ============================================================
__global__ void transpose_wo(const float* __restrict__ src)
{
    __shared__ float tile[32][33];
    int tx = threadIdx.x, ty = threadIdx.y;
    int x = blockIdx.x*32 + tx;
    int y = blockIdx.y*32 + ty;
    #pragma unroll
    for (int i = 0; i < 32; i += 8)
        tile[ty+i][tx] = src[(size_t)(y+i)*Dd + x];
    __syncthreads();
    int x2 = blockIdx.y*32 + tx;
    int y2 = blockIdx.x*32 + ty;
    #pragma unroll
    for (int i = 0; i < 32; i += 8)
        g_WoT[(size_t)(y2+i)*(H*DK) + x2] = __uint_as_float(f2tf32(tile[tx][ty+i]));
}

// ============================================================
extern "C" void kernel_launch(void* const* d_in, const int* in_sizes, int n_in,
                              void* d_out, int out_size)
{
    const float* X  = (const float*)d_in[0];
    const float* wG = (const float*)d_in[1];
    const float* bG = (const float*)d_in[2];
    const float* wK = (const float*)d_in[3];
    const float* wV = (const float*)d_in[4];
    const float* wQ = (const float*)d_in[5];
    const float* wO = (const float*)d_in[6];
    const float* iK = (const float*)d_in[7];
    const float* iV = (const float*)d_in[8];
    float* out = (float*)d_out;

    cudaMemcpyToSymbolAsync(g_bias, bG, 32*sizeof(float), 0, cudaMemcpyDeviceToDevice, 0);

    float *dBias, *dP, *dY, *dWoT;
    uint32_t *dXtf, *dWcat;
    cudaGetSymbolAddress((void**)&dWcat, g_Wcat);
    cudaGetSymbolAddress((void**)&dBias, g_bias);
    cudaGetSymbolAddress((void**)&dP,    g_P);
    cudaGetSymbolAddress((void**)&dY,    g_Y);
    cudaGetSymbolAddress((void**)&dWoT,  g_WoT);
    cudaGetSymbolAddress((void**)&dXtf,  g_Xtf);

    // pack + pre-round operands to tf32
    pack_weights<<<(PC*Dd/4 + 255)/256, 256>>>(
        (const float4*)wG, (const float4*)wK, (const float4*)wV, (const float4*)wQ);
    cvt_x<<<((NT*Dd/4) + 255)/256, 256>>>((const float4*)X, (uint4*)dXtf, NT*Dd/4);
    transpose_wo<<<dim3(Dd/32, (H*DK)/32), dim3(32,8)>>>(wO);

    int gsmem = STAGES*(128 + 128)*16*4;   // 49152 B
    cudaFuncSetAttribute(mgemm<true>,  cudaFuncAttributeMaxDynamicSharedMemorySize, gsmem);
    cudaFuncSetAttribute(mgemm<false>, cudaFuncAttributeMaxDynamicSharedMemorySize, gsmem);

    // 1) fused projection GEMM
    mgemm<true><<<dim3((PC+127)/128, NT/128), 256, gsmem>>>(
        dXtf, dWcat, dP, NT, PC, Dd, dBias, 32);

    // 2) gates
    gate_combine<<<NT, 256>>>();

    // 3) scans
    scan_kernel<<<Nb*E*Lw, 128>>>(iK, iV);

    // 4) attention
    int smem_bytes = 2*WW*SST*sizeof(float);
    cudaFuncSetAttribute(attention_kernel, cudaFuncAttributeMaxDynamicSharedMemorySize, smem_bytes);
    attention_kernel<<<Nb*(T/TQ), 256, smem_bytes>>>();

    // 5) output projection
    mgemm<false><<<dim3(Dd/128, NT/128), 256, gsmem>>>(
        (const uint32_t*)dY, (const uint32_t*)dWoT, out, NT, Dd, H*DK, nullptr, 0);
}

// round 7
// speedup vs baseline: 3.3994x; 1.0884x over previous
#include <cuda_runtime.h>
#include <cuda_fp16.h>
#include <math.h>
#include <stdint.h>

// ---- problem constants ----
#define Nb   2
#define T    4096
#define Dd   1024
#define H    8
#define E    4
#define Lw   32
#define TC   128
#define DK   64
#define NT   (Nb*T)       // 8192
#define PC   1568         // 32 G + 512 K + 512 V + 512 Q
#define RLEN (Lw + T)     // 4128

#define TQ   32
#define WW   63
#define SST  260

#define STAGES 3
// one pipeline stage = 256 rows x 32 halves = 16384 bytes = 4096 uint32
#define STAGE_BYTES 16384
#define STAGE_U32   4096

// ---- device scratch ----
__device__ __half  g_Wh[(size_t)PC*Dd];     // fp16 weights (concat)
__device__ float   g_bias[PC];
__device__ __half  g_Xh[(size_t)NT*Dd];     // fp16 X
__device__ float   g_P[(size_t)NT*PC];
__device__ float   g_A[Nb*E*T];
__device__ float   g_gK[(size_t)Nb*E*T*DK];
__device__ float   g_gV[(size_t)Nb*E*T*DK];
__device__ float   g_recK[(size_t)Nb*E*RLEN*DK];
__device__ float   g_recV[(size_t)Nb*E*RLEN*DK];
__device__ __half  g_Yh[(size_t)NT*H*DK];   // fp16 attention output
__device__ __half  g_WoTh[(size_t)Dd*H*DK]; // fp16 w_O^T

// ============================================================
// helpers
// ============================================================
__device__ __forceinline__ void mma_f16(float4& c,
    uint32_t a0, uint32_t a1, uint32_t a2, uint32_t a3,
    uint32_t b0, uint32_t b1)
{
    asm volatile("mma.sync.aligned.m16n8k16.row.col.f32.f16.f16.f32 "
        "{%0,%1,%2,%3}, {%4,%5,%6,%7}, {%8,%9}, {%0,%1,%2,%3};"
        : "+f"(c.x), "+f"(c.y), "+f"(c.z), "+f"(c.w)
        : "r"(a0), "r"(a1), "r"(a2), "r"(a3), "r"(b0), "r"(b1));
}

__device__ __forceinline__ void cp16(uint32_t dst, const void* src, int sz) {
    asm volatile("cp.async.cg.shared.global [%0], [%1], 16, %2;"
                 :: "r"(dst), "l"(src), "r"(sz));
}
__device__ __forceinline__ void cp_commit() { asm volatile("cp.async.commit_group;"); }
__device__ __forceinline__ void cp_wait1()  { asm volatile("cp.async.wait_group 1;"); }

// ============================================================
// FP16 GEMM (NT): C[M][Nn] = A[M][K] * B[Nn][K]^T, fp32 accum.
// BM=128, BN=128, BK=32 (fp16). 256 threads, 8 warps of 64x32.
// 3-stage cp.async pipeline, 2 CTAs/SM.
// Smem stage: rows [0,128)=A, [128,256)=B, 32 halves (64 B) per row.
// Fragment loads: uint4 per lane at uint32 offset tig*4 -> 4 half-pairs
// feeding TWO m16n8k16 MMAs; the k-permutation (lane,slot)->k-pair is
// identical for A and B, so the K-sum is exact under reassociation.
// ============================================================
template<bool ACT>
__global__ __launch_bounds__(256, 2) void mgemm(
    const __half* __restrict__ A, const __half* __restrict__ B,
    float* __restrict__ C, int M, int Nn, int K,
    const float* __restrict__ bias, int act_cols)
{
    extern __shared__ __align__(16) __half hsm[];

    int tid  = threadIdx.x;
    int bm   = blockIdx.y, bn = blockIdx.x;
    int warp = tid >> 5, lane = tid & 31;
    int wm   = (warp >> 2) * 64;          // 0,64
    int wn   = (warp & 3) * 32;           // 0,32,64,96
    int gid  = lane >> 2, tig = lane & 3;

    // staging: thread = one row (0..255) of the combined stage, 4 cp16
    int srow = tid;                       // 0..255
    bool isA = srow < 128;
    int arow = bm*128 + srow;             // if A
    int brow = bn*128 + (srow - 128);     // if B
    int sz   = isA ? 16 : ((brow < Nn) ? 16 : 0);
    const __half* src = isA ? (A + (size_t)arow*K)
                            : (B + (size_t)(sz ? brow : 0)*K);

    uint32_t sbase = (uint32_t)__cvta_generic_to_shared(hsm);
    uint32_t sdst  = sbase + srow*64;     // row base (bytes) in stage 0

    auto stage = [&](int kt, int s) {
        uint32_t d = sdst + s*STAGE_BYTES;
        const __half* p = src + kt*32;
        #pragma unroll
        for (int i = 0; i < 4; ++i)
            cp16(d + i*16, p + i*8, sz);
        cp_commit();
    };

    float4 acc[4][4];
    #pragma unroll
    for (int i = 0; i < 4; ++i)
        #pragma unroll
        for (int j = 0; j < 4; ++j) acc[i][j] = make_float4(0.f,0.f,0.f,0.f);

    int nk = K / 32;
    stage(0, 0);
    stage(1, 1);

    const uint32_t* Hs = (const uint32_t*)hsm;   // uint32 (half2) view

    for (int kt = 0; kt < nk; ++kt) {
        cp_wait1();
        __syncthreads();

        int buf = kt % STAGES;
        const uint32_t* as = Hs + buf*STAGE_U32;   // A rows 0..127
        const uint32_t* bs = as + 128*16;          // B rows start at row 128 (16 u32/row)

        // fragment loads: row stride = 32 halves = 16 uint32
        uint4 alo[4], ahi[4], bf[4];
        #pragma unroll
        for (int mf = 0; mf < 4; ++mf) {
            alo[mf] = *(const uint4*)&as[(wm + mf*16 + gid    )*16 + tig*4];
            ahi[mf] = *(const uint4*)&as[(wm + mf*16 + gid + 8)*16 + tig*4];
        }
        #pragma unroll
        for (int nf = 0; nf < 4; ++nf)
            bf[nf] = *(const uint4*)&bs[(wn + nf*8 + gid)*16 + tig*4];

        #pragma unroll
        for (int mf = 0; mf < 4; ++mf)
            #pragma unroll
            for (int nf = 0; nf < 4; ++nf) {
                mma_f16(acc[mf][nf], alo[mf].x, ahi[mf].x, alo[mf].y, ahi[mf].y,
                                     bf[nf].x, bf[nf].y);
                mma_f16(acc[mf][nf], alo[mf].z, ahi[mf].z, alo[mf].w, ahi[mf].w,
                                     bf[nf].z, bf[nf].w);
            }

        int kn = kt + (STAGES - 1);
        if (kn < nk) stage(kn, kn % STAGES);
        else cp_commit();
    }

    // epilogue: (c.x,c.y) -> (row gid, col 2t,2t+1); (c.z,c.w) -> row gid+8
    #pragma unroll
    for (int mf = 0; mf < 4; ++mf) {
        int row = bm*128 + wm + mf*16 + gid;
        #pragma unroll
        for (int nf = 0; nf < 4; ++nf) {
            int col = bn*128 + wn + nf*8 + tig*2;
            if (col < Nn) {
                float4 v = acc[mf][nf];
                if (ACT && col < act_cols) {
                    v.x = 1.f/(1.f + __expf(-(v.x + bias[col])));
                    v.y = 1.f/(1.f + __expf(-(v.y + bias[col+1])));
                    v.z = 1.f/(1.f + __expf(-(v.z + bias[col])));
                    v.w = 1.f/(1.f + __expf(-(v.w + bias[col+1])));
                }
                *(float2*)(C + (size_t)row*Nn + col)     = make_float2(v.x, v.y);
                *(float2*)(C + (size_t)(row+8)*Nn + col) = make_float2(v.z, v.w);
            }
        }
    }
}

// ============================================================
// fused weight pack + fp16 convert
// ============================================================
__global__ void pack_weights(const float4* __restrict__ wG,
                             const float4* __restrict__ wK,
                             const float4* __restrict__ wV,
                             const float4* __restrict__ wQ)
{
    int i = blockIdx.x*blockDim.x + threadIdx.x;   // float4 index
    if (i >= PC*Dd/4) return;
    int row = i / (Dd/4);
    int c4  = i - row*(Dd/4);
    float4 v;
    if (row < 32)        v = wG[row*(Dd/4) + c4];
    else if (row < 544)  v = wK[(row-32)*(Dd/4) + c4];
    else if (row < 1056) v = wV[(row-544)*(Dd/4) + c4];
    else                 v = wQ[(row-1056)*(Dd/4) + c4];
    __half2* o = (__half2*)(g_Wh + (size_t)i*4);
    o[0] = __floats2half2_rn(v.x, v.y);
    o[1] = __floats2half2_rn(v.z, v.w);
}

__global__ void cvt_x(const float4* __restrict__ X, int n4)
{
    int i = blockIdx.x*blockDim.x + threadIdx.x;
    if (i < n4) {
        float4 v = X[i];
        __half2* o = (__half2*)(g_Xh + (size_t)i*4);
        o[0] = __floats2half2_rn(v.x, v.y);
        o[1] = __floats2half2_rn(v.z, v.w);
    }
}

// ============================================================
// Gate combine
// ============================================================
__global__ __launch_bounds__(256) void gate_combine()
{
    int row = blockIdx.x;
    int n = row / T, t = row - n*T;
    __shared__ float sG[H*E];
    int tid = threadIdx.x;
    const float* Pr = g_P + (size_t)row*PC;
    if (tid < H*E) sG[tid] = Pr[tid];
    __syncthreads();
    if (tid < E) {
        float s = 0.f;
        #pragma unroll
        for (int h = 0; h < H; ++h) s += sG[h*E + tid];
        g_A[(n*E + tid)*T + t] = 1.f - fminf(s, 1.f);
    }
    int e = tid >> 6, d = tid & 63;
    float sk = 0.f, sv = 0.f;
    #pragma unroll
    for (int h = 0; h < H; ++h) {
        float g = sG[h*E + e];
        sk = fmaf(g, Pr[32  + h*64 + d], sk);
        sv = fmaf(g, Pr[544 + h*64 + d], sv);
    }
    size_t o = ((size_t)(n*E + e)*T + t)*DK + d;
    g_gK[o] = sk;
    g_gV[o] = sv;
}

// ============================================================
// Scan (pipelined)
// ============================================================
__global__ __launch_bounds__(128) void scan_kernel(
    const float* __restrict__ initK, const float* __restrict__ initV)
{
    __shared__ float sa[TC];
    int b = blockIdx.x;
    int l = b % Lw, e = (b / Lw) % E, n = b / (Lw*E);
    int tid = threadIdx.x;
    bool isV = tid >= 64;
    int d = tid & 63;
    const float* init = isV ? initV : initK;
    const float* g    = isV ? g_gV  : g_gK;
    float*       rec  = isV ? g_recV : g_recK;

    size_t base = (size_t)(n*E + e);
    int t0 = l*TC;
    const float* Arow = g_A + base*T + t0;
    if (tid < TC) sa[tid] = Arow[tid];
    __syncthreads();

    float st = init[(e*Lw + l)*DK + d];
    rec[(base*RLEN + l)*DK + d] = st;
    const float* grow   = g   + (base*T   + t0)*(size_t)DK + d;
    float*       recrow = rec + (base*RLEN + Lw + t0)*(size_t)DK + d;

    float gbuf[8];
    #pragma unroll
    for (int j = 0; j < 8; ++j) gbuf[j] = grow[(size_t)j*DK];

    for (int c0 = 0; c0 < TC; c0 += 8) {
        float gn[8];
        if (c0 + 8 < TC) {
            #pragma unroll
            for (int j = 0; j < 8; ++j) gn[j] = grow[(size_t)(c0+8+j)*DK];
        }
        #pragma unroll
        for (int j = 0; j < 8; ++j) {
            st = fmaf(sa[c0+j], st, gbuf[j]);
            recrow[(size_t)(c0+j)*DK] = st;
        }
        #pragma unroll
        for (int j = 0; j < 8; ++j) gbuf[j] = gn[j];
    }
}

// ============================================================
// Attention: online softmax; writes Y directly as fp16
// ============================================================
extern __shared__ float sm_att[];

__global__ __launch_bounds__(256, 1) void attention_kernel()
{
    float* Ks = sm_att;
    float* Vs = sm_att + WW*SST;
    int bid = blockIdx.x;
    int n    = bid / (T/TQ);
    int tile = bid % (T/TQ);
    int t0 = tile*TQ;
    int tid = threadIdx.x;

    for (int i = tid; i < WW*E*16; i += 256) {
        int w   = i >> 6;
        int rem = i & 63;
        int e = rem >> 4, d4 = rem & 15;
        size_t go = (((size_t)(n*E + e))*RLEN + (1 + t0 + w))*DK + d4*4;
        float4 kv = *(const float4*)(g_recK + go);
        float4 vv = *(const float4*)(g_recV + go);
        int so = w*SST + e*64 + d4*4;
        *(float4*)(Ks + so) = kv;
        *(float4*)(Vs + so) = vv;
    }
    __syncthreads();

    int h = tid & 7, tq = tid >> 3;
    int t = t0 + tq;
    float4 q[16];
    const float* Qp = g_P + (size_t)(n*T + t)*PC + 1056 + h*64;
    #pragma unroll
    for (int i = 0; i < 16; ++i) q[i] = *(const float4*)(Qp + i*4);

    float m = -1e30f, sum = 0.f;
    float4 acc[16];
    #pragma unroll
    for (int i = 0; i < 16; ++i) acc[i] = make_float4(0.f,0.f,0.f,0.f);

    for (int e = 0; e < E; ++e) {
        for (int l = 0; l < Lw; ++l) {
            const float* kp = Ks + (tq + l)*SST + e*64;
            float s = 0.f;
            #pragma unroll
            for (int i = 0; i < 16; ++i) {
                float4 k4 = *(const float4*)(kp + i*4);
                s = fmaf(q[i].x,k4.x, fmaf(q[i].y,k4.y,
                    fmaf(q[i].z,k4.z, fmaf(q[i].w,k4.w, s))));
            }
            s *= 0.125f;
            if (s > m) {
                float f = __expf(m - s);
                sum *= f;
                #pragma unroll
                for (int i = 0; i < 16; ++i) {
                    acc[i].x *= f; acc[i].y *= f; acc[i].z *= f; acc[i].w *= f;
                }
                m = s;
            }
            float p = __expf(s - m);
            sum += p;
            const float* vp = Vs + (tq + l)*SST + e*64;
            #pragma unroll
            for (int i = 0; i < 16; ++i) {
                float4 v4 = *(const float4*)(vp + i*4);
                acc[i].x = fmaf(p, v4.x, acc[i].x);
                acc[i].y = fmaf(p, v4.y, acc[i].y);
                acc[i].z = fmaf(p, v4.z, acc[i].z);
                acc[i].w = fmaf(p, v4.w, acc[i].w);
            }
        }
    }

    float inv = 1.f / sum;
    __half2* Yp = (__half2*)(g_Yh + (size_t)(n*T + t)*(H*DK) + h*64);
    #pragma unroll
    for (int i = 0; i < 16; ++i) {
        Yp[i*2]   = __floats2half2_rn(acc[i].x*inv, acc[i].y*inv);
        Yp[i*2+1] = __floats2half2_rn(acc[i].z*inv, acc[i].w*inv);
    }
}

// ============================================================
// w_O transpose: (512,1024) -> (1024,512), fp16 output
// ============================================================
__global__ void transpose_wo(const float* __restrict__ src)
{
    __shared__ float tile[32][33];
    int tx = threadIdx.x, ty = threadIdx.y;
    int x = blockIdx.x*32 + tx;
    int y = blockIdx.y*32 + ty;
    #pragma unroll
    for (int i = 0; i < 32; i += 8)
        tile[ty+i][tx] = src[(size_t)(y+i)*Dd + x];
    __syncthreads();
    int x2 = blockIdx.y*32 + tx;
    int y2 = blockIdx.x*32 + ty;
    #pragma unroll
    for (int i = 0; i < 32; i += 8)
        g_WoTh[(size_t)(y2+i)*(H*DK) + x2] = __float2half_rn(tile[tx][ty+i]);
}

// ============================================================
extern "C" void kernel_launch(void* const* d_in, const int* in_sizes, int n_in,
                              void* d_out, int out_size)
{
    const float* X  = (const float*)d_in[0];
    const float* wG = (const float*)d_in[1];
    const float* bG = (const float*)d_in[2];
    const float* wK = (const float*)d_in[3];
    const float* wV = (const float*)d_in[4];
    const float* wQ = (const float*)d_in[5];
    const float* wO = (const float*)d_in[6];
    const float* iK = (const float*)d_in[7];
    const float* iV = (const float*)d_in[8];
    float* out = (float*)d_out;

    cudaMemcpyToSymbolAsync(g_bias, bG, 32*sizeof(float), 0, cudaMemcpyDeviceToDevice, 0);

    float *dBias, *dP;
    __half *dXh, *dWh, *dYh, *dWoTh;
    cudaGetSymbolAddress((void**)&dWh,   g_Wh);
    cudaGetSymbolAddress((void**)&dBias, g_bias);
    cudaGetSymbolAddress((void**)&dP,    g_P);
    cudaGetSymbolAddress((void**)&dYh,   g_Yh);
    cudaGetSymbolAddress((void**)&dWoTh, g_WoTh);
    cudaGetSymbolAddress((void**)&dXh,   g_Xh);

    // pack + convert operands to fp16
    pack_weights<<<(PC*Dd/4 + 255)/256, 256>>>(
        (const float4*)wG, (const float4*)wK, (const float4*)wV, (const float4*)wQ);
    cvt_x<<<((NT*Dd/4) + 255)/256, 256>>>((const float4*)X, NT*Dd/4);
    transpose_wo<<<dim3(Dd/32, (H*DK)/32), dim3(32,8)>>>(wO);

    int gsmem = STAGES*STAGE_BYTES;   // 49152 B
    cudaFuncSetAttribute(mgemm<true>,  cudaFuncAttributeMaxDynamicSharedMemorySize, gsmem);
    cudaFuncSetAttribute(mgemm<false>, cudaFuncAttributeMaxDynamicSharedMemorySize, gsmem);

    // 1) fused projection GEMM (fp16 tensor cores, fp32 accum)
    mgemm<true><<<dim3((PC+127)/128, NT/128), 256, gsmem>>>(
        dXh, dWh, dP, NT, PC, Dd, dBias, 32);

    // 2) gates
    gate_combine<<<NT, 256>>>();

    // 3) scans
    scan_kernel<<<Nb*E*Lw, 128>>>(iK, iV);

    // 4) attention
    int smem_bytes = 2*WW*SST*sizeof(float);
    cudaFuncSetAttribute(attention_kernel, cudaFuncAttributeMaxDynamicSharedMemorySize, smem_bytes);
    attention_kernel<<<Nb*(T/TQ), 256, smem_bytes>>>();

    // 5) output projection
    mgemm<false><<<dim3(Dd/128, NT/128), 256, gsmem>>>(
        dYh, dWoTh, out, NT, Dd, H*DK, nullptr, 0);
}